// round 13
// baseline (speedup 1.0000x reference)
#include <cuda_runtime.h>
#include <cstdint>

// BallQuery via uniform grid, 3 graph nodes:
//   1) cudaMemsetAsync zero of cell counters (memset node — no kernel ramp)
//   2) scatter kernel (128 blocks, barrier-free)
//   3) query kernel (1024 blocks): lane-parallel pruned cell list, ballot
//      compaction, tri-width bitonic canonicalization (32/64/128).
// B=4, N1=2048, N2=8192, K=64, radius 0.1, output float32 (index as float).

#define BQ_B      4
#define BQ_N1     2048
#define BQ_N2     8192
#define BQ_K      64
#define GRID      10
#define NCELL     (GRID * GRID * GRID)
#define CELL_CAP  64
#define ADDR_CAP  512
#define HIT_CAP   128

__device__ static int    g_counts[BQ_B * NCELL];
__device__ static float4 g_items[BQ_B * NCELL * CELL_CAP];

__global__ __launch_bounds__(256)
void bq_scatter_kernel(const float* __restrict__ key)
{
    const int tid = blockIdx.x * 256 + threadIdx.x;   // exactly 32768 threads
    int b = tid >> 13;
    int j = tid & (BQ_N2 - 1);
    const float* kp = key + (size_t)tid * 3;
    float x = kp[0], y = kp[1], z = kp[2];
    int cx = min((int)(x * 10.0f), GRID - 1);
    int cy = min((int)(y * 10.0f), GRID - 1);
    int cz = min((int)(z * 10.0f), GRID - 1);
    int cell = (cz * GRID + cy) * GRID + cx;
    int slot = atomicAdd(&g_counts[b * NCELL + cell], 1);
    if (slot < CELL_CAP)
        g_items[(b * NCELL + cell) * CELL_CAP + slot] =
            make_float4(x, y, z, __int_as_float(j));
}

__global__ __launch_bounds__(256)
void bq_query_kernel(const float* __restrict__ query,
                     float* __restrict__ out)
{
    __shared__ int s_addr[8][ADDR_CAP];
    __shared__ int s_hbuf[8][HIT_CAP];

    const int wid  = threadIdx.x >> 5;
    const int lane = threadIdx.x & 31;
    const int w    = blockIdx.x * 8 + wid;       // query id
    const int b    = w / BQ_N1;
    const int q    = w - b * BQ_N1;

    const float* qp = query + (size_t)w * 3;
    const float qx = qp[0];
    const float qy = qp[1];
    const float qz = qp[2];

    const int cx = min((int)(qx * 10.0f), GRID - 1);
    const int cy = min((int)(qy * 10.0f), GRID - 1);
    const int cz = min((int)(qz * 10.0f), GRID - 1);

    const float r2 = 0.1f * 0.1f;                // jnp.float32(0.1)**2

    // ---- lane-parallel neighbor-cell enumeration + box-distance pruning ----
    int cnt_l = 0, base_l = 0;
    if (lane < 27) {
        int x = cx + (lane % 3) - 1;
        int y = cy + ((lane / 3) % 3) - 1;
        int z = cz + (lane / 9) - 1;
        if (x >= 0 && x < GRID && y >= 0 && y < GRID && z >= 0 && z < GRID) {
            // Conservative min distance^2 to the padded cell box
            // (pad 1e-5 >> ~1e-6 fuzz of int(x*10.f) cell assignment).
            float lox = x * 0.1f - 1e-5f, hix = x * 0.1f + 0.1f + 1e-5f;
            float loy = y * 0.1f - 1e-5f, hiy = y * 0.1f + 0.1f + 1e-5f;
            float loz = z * 0.1f - 1e-5f, hiz = z * 0.1f + 0.1f + 1e-5f;
            float ddx = fmaxf(fmaxf(lox - qx, qx - hix), 0.0f);
            float ddy = fmaxf(fmaxf(loy - qy, qy - hiy), 0.0f);
            float ddz = fmaxf(fmaxf(loz - qz, qz - hiz), 0.0f);
            float md2 = ddx * ddx + ddy * ddy + ddz * ddz;
            if (md2 < r2) {
                int cell = (z * GRID + y) * GRID + x;
                cnt_l  = min(g_counts[b * NCELL + cell], CELL_CAP);
                base_l = cell * CELL_CAP;
            }
        }
    }
    int inc = cnt_l;
    #pragma unroll
    for (int d = 1; d < 32; d <<= 1) {
        int n = __shfl_up_sync(0xffffffffu, inc, d);
        if (lane >= d) inc += n;
    }
    int ex = inc - cnt_l;
    int T  = __shfl_sync(0xffffffffu, inc, 31);
    for (int i = 0; i < cnt_l; i++) {
        int s = ex + i;
        if (s < ADDR_CAP) s_addr[wid][s] = base_l + i;
    }
    T = min(T, ADDR_CAP);
    __syncwarp();

    // ---- test candidates (2 per lane per round), compact hits to smem ----
    const unsigned lt_mask = (1u << lane) - 1u;
    const float4* items_b = g_items + (size_t)b * NCELL * CELL_CAP;

    int hcnt = 0;
    for (int i0 = 0; i0 < T; i0 += 64) {
        int ia  = i0 + lane;
        int ib2 = i0 + 32 + lane;
        bool hita = false, hitb = false;
        int ka = 0, kb2 = 0;
        if (ia < T) {
            float4 kv = items_b[s_addr[wid][ia]];
            // strict f32, no FMA, left-to-right — matches jax boundaries
            float dx = __fsub_rn(qx, kv.x);
            float dy = __fsub_rn(qy, kv.y);
            float dz = __fsub_rn(qz, kv.z);
            float d2 = __fadd_rn(__fadd_rn(__fmul_rn(dx, dx),
                                           __fmul_rn(dy, dy)),
                                 __fmul_rn(dz, dz));
            hita = d2 < r2;
            ka   = __float_as_int(kv.w);
        }
        if (ib2 < T) {
            float4 kv = items_b[s_addr[wid][ib2]];
            float dx = __fsub_rn(qx, kv.x);
            float dy = __fsub_rn(qy, kv.y);
            float dz = __fsub_rn(qz, kv.z);
            float d2 = __fadd_rn(__fadd_rn(__fmul_rn(dx, dx),
                                           __fmul_rn(dy, dy)),
                                 __fmul_rn(dz, dz));
            hitb = d2 < r2;
            kb2  = __float_as_int(kv.w);
        }
        unsigned m0 = __ballot_sync(0xffffffffu, hita);
        unsigned m1 = __ballot_sync(0xffffffffu, hitb);
        if (hita) {
            int slot = hcnt + __popc(m0 & lt_mask);
            if (slot < HIT_CAP) s_hbuf[wid][slot] = ka;
        }
        int base1 = hcnt + __popc(m0);
        if (hitb) {
            int slot = base1 + __popc(m1 & lt_mask);
            if (slot < HIT_CAP) s_hbuf[wid][slot] = kb2;
        }
        hcnt = base1 + __popc(m1);
    }
    hcnt = min(hcnt, HIT_CAP);
    __syncwarp();

    float* op = out + ((size_t)b * BQ_N1 + q) * BQ_K;

    if (hcnt <= 32) {
        // ---- 32-wide bitonic sort (1 reg/lane, 15 stages) ----
        int v0 = (lane < hcnt) ? s_hbuf[wid][lane] : 0x7FFFFFFF;
        #pragma unroll
        for (int k = 2; k <= 32; k <<= 1) {
            #pragma unroll
            for (int j = 16; j > 0; j >>= 1) {
                if (j >= k) continue;
                int other = __shfl_xor_sync(0xffffffffu, v0, j);
                bool up    = ((lane & k) == 0);      // k==32 -> always true
                bool lower = ((lane & j) == 0);
                int lo = min(v0, other), hi = max(v0, other);
                v0 = (lower == up) ? lo : hi;
            }
        }
        int minv = __shfl_sync(0xffffffffu, v0, 0);
        int fill = (hcnt > 0) ? minv : 0;
        op[lane]      = (float)((lane < hcnt) ? v0 : fill);
        op[lane + 32] = (float)fill;                 // slots 32..63 all past hcnt
    } else if (hcnt <= 64) {
        // ---- 64-wide bitonic sort (2 regs/lane) ----
        int v[2];
        #pragma unroll
        for (int r = 0; r < 2; r++) {
            int e = lane + 32 * r;
            v[r] = (e < hcnt) ? s_hbuf[wid][e] : 0x7FFFFFFF;
        }
        #pragma unroll
        for (int k = 2; k <= 64; k <<= 1) {
            #pragma unroll
            for (int j = 64; j > 0; j >>= 1) {
                if (j >= k) continue;
                if (j < 32) {
                    #pragma unroll
                    for (int r = 0; r < 2; r++) {
                        int other = __shfl_xor_sync(0xffffffffu, v[r], j);
                        bool up    = (((lane + 32 * r) & k) == 0);
                        bool lower = ((lane & j) == 0);
                        int lo = min(v[r], other), hi = max(v[r], other);
                        v[r] = (lower == up) ? lo : hi;
                    }
                } else {            // j == 32: pair (lane, lane+32) in-lane
                    bool up = ((lane & k) == 0);     // k==64 -> always true
                    int lo = min(v[0], v[1]), hi = max(v[0], v[1]);
                    v[0] = up ? lo : hi;
                    v[1] = up ? hi : lo;
                }
            }
        }
        int minv = __shfl_sync(0xffffffffu, v[0], 0);
        int fill = (hcnt > 0) ? minv : 0;
        int e0 = lane, e1 = lane + 32;
        op[e0] = (float)((e0 < hcnt) ? v[0] : fill);
        op[e1] = (float)((e1 < hcnt) ? v[1] : fill);
    } else {
        // ---- rare path: full 128-wide bitonic sort (4 regs/lane) ----
        int v[4];
        #pragma unroll
        for (int r = 0; r < 4; r++) {
            int e = lane + 32 * r;
            v[r] = (e < hcnt) ? s_hbuf[wid][e] : 0x7FFFFFFF;
        }
        #pragma unroll
        for (int k = 2; k <= 128; k <<= 1) {
            #pragma unroll
            for (int j = 64; j > 0; j >>= 1) {
                if (j >= k) continue;
                if (j < 32) {
                    #pragma unroll
                    for (int r = 0; r < 4; r++) {
                        int other = __shfl_xor_sync(0xffffffffu, v[r], j);
                        bool up    = (((lane + 32 * r) & k) == 0);
                        bool lower = ((lane & j) == 0);
                        int lo = min(v[r], other), hi = max(v[r], other);
                        v[r] = (lower == up) ? lo : hi;
                    }
                } else {
                    int rd = j >> 5;
                    #pragma unroll
                    for (int r = 0; r < 4; r++) {
                        if ((r & rd) == 0) {
                            int r2i = r | rd;
                            bool up = (((lane + 32 * r) & k) == 0);
                            int a = v[r], bb = v[r2i];
                            int lo = min(a, bb), hi = max(a, bb);
                            v[r]   = up ? lo : hi;
                            v[r2i] = up ? hi : lo;
                        }
                    }
                }
            }
        }
        int minv = __shfl_sync(0xffffffffu, v[0], 0);
        int fill = (hcnt > 0) ? minv : 0;
        int e0 = lane, e1 = lane + 32;
        op[e0] = (float)((e0 < hcnt) ? v[0] : fill);
        op[e1] = (float)((e1 < hcnt) ? v[1] : fill);
    }
}

extern "C" void kernel_launch(void* const* d_in, const int* in_sizes, int n_in,
                              void* d_out, int out_size)
{
    const float* query = (const float*)d_in[0];
    const float* key   = (const float*)d_in[1];
    if (n_in >= 2 && in_sizes[0] > in_sizes[1]) {   // belt-and-braces
        key   = (const float*)d_in[0];
        query = (const float*)d_in[1];
    }
    float* out = (float*)d_out;

    // Zero the cell counters with a memset node (no kernel-launch ramp, no
    // grid barrier). cudaGetSymbolAddress is a host-side lookup: no alloc,
    // no stream work; cudaMemsetAsync on the capture stream becomes a
    // graph memset node.
    void* counts_ptr = nullptr;
    cudaGetSymbolAddress(&counts_ptr, g_counts);
    cudaMemsetAsync(counts_ptr, 0, sizeof(int) * BQ_B * NCELL, 0);

    bq_scatter_kernel<<<BQ_B * BQ_N2 / 256, 256>>>(key);
    bq_query_kernel<<<BQ_B * BQ_N1 / 8, 256>>>(query, out);
}

// round 15
// speedup vs baseline: 1.3928x; 1.3928x over previous
#include <cuda_runtime.h>
#include <cstdint>

// BallQuery via uniform grid, 3 graph nodes:
//   1) cudaMemsetAsync zero of cell counters (memset node)
//   2) scatter kernel (128 blocks, barrier-free)
//   3) query kernel — EXACT R12 version (lane-parallel pruned cell list,
//      2-per-lane ballot compaction, dual-width 64/128 bitonic sort).
// B=4, N1=2048, N2=8192, K=64, radius 0.1, output float32 (index as float).

#define BQ_B      4
#define BQ_N1     2048
#define BQ_N2     8192
#define BQ_K      64
#define GRID      10
#define NCELL     (GRID * GRID * GRID)
#define CELL_CAP  64
#define ADDR_CAP  512
#define HIT_CAP   128

__device__ static int    g_counts[BQ_B * NCELL];
__device__ static float4 g_items[BQ_B * NCELL * CELL_CAP];

__global__ __launch_bounds__(256)
void bq_scatter_kernel(const float* __restrict__ key)
{
    const int tid = blockIdx.x * 256 + threadIdx.x;   // exactly 32768 threads
    int b = tid >> 13;
    int j = tid & (BQ_N2 - 1);
    const float* kp = key + (size_t)tid * 3;
    float x = kp[0], y = kp[1], z = kp[2];
    int cx = min((int)(x * 10.0f), GRID - 1);
    int cy = min((int)(y * 10.0f), GRID - 1);
    int cz = min((int)(z * 10.0f), GRID - 1);
    int cell = (cz * GRID + cy) * GRID + cx;
    int slot = atomicAdd(&g_counts[b * NCELL + cell], 1);
    if (slot < CELL_CAP)
        g_items[(b * NCELL + cell) * CELL_CAP + slot] =
            make_float4(x, y, z, __int_as_float(j));
}

__global__ __launch_bounds__(256)
void bq_query_kernel(const float* __restrict__ query,
                     float* __restrict__ out)
{
    __shared__ int s_addr[8][ADDR_CAP];
    __shared__ int s_hbuf[8][HIT_CAP];

    const int wid  = threadIdx.x >> 5;
    const int lane = threadIdx.x & 31;
    const int w    = blockIdx.x * 8 + wid;       // query id
    const int b    = w / BQ_N1;
    const int q    = w - b * BQ_N1;

    const float* qp = query + (size_t)w * 3;
    const float qx = qp[0];
    const float qy = qp[1];
    const float qz = qp[2];

    const int cx = min((int)(qx * 10.0f), GRID - 1);
    const int cy = min((int)(qy * 10.0f), GRID - 1);
    const int cz = min((int)(qz * 10.0f), GRID - 1);

    const float r2 = 0.1f * 0.1f;                // jnp.float32(0.1)**2

    // ---- lane-parallel neighbor-cell enumeration + box-distance pruning ----
    int cnt_l = 0, base_l = 0;
    if (lane < 27) {
        int x = cx + (lane % 3) - 1;
        int y = cy + ((lane / 3) % 3) - 1;
        int z = cz + (lane / 9) - 1;
        if (x >= 0 && x < GRID && y >= 0 && y < GRID && z >= 0 && z < GRID) {
            // Conservative min distance^2 to the padded cell box
            // (pad 1e-5 >> ~1e-6 fuzz of int(x*10.f) cell assignment).
            float lox = x * 0.1f - 1e-5f, hix = x * 0.1f + 0.1f + 1e-5f;
            float loy = y * 0.1f - 1e-5f, hiy = y * 0.1f + 0.1f + 1e-5f;
            float loz = z * 0.1f - 1e-5f, hiz = z * 0.1f + 0.1f + 1e-5f;
            float ddx = fmaxf(fmaxf(lox - qx, qx - hix), 0.0f);
            float ddy = fmaxf(fmaxf(loy - qy, qy - hiy), 0.0f);
            float ddz = fmaxf(fmaxf(loz - qz, qz - hiz), 0.0f);
            float md2 = ddx * ddx + ddy * ddy + ddz * ddz;
            if (md2 < r2) {
                int cell = (z * GRID + y) * GRID + x;
                cnt_l  = min(g_counts[b * NCELL + cell], CELL_CAP);
                base_l = cell * CELL_CAP;
            }
        }
    }
    int inc = cnt_l;
    #pragma unroll
    for (int d = 1; d < 32; d <<= 1) {
        int n = __shfl_up_sync(0xffffffffu, inc, d);
        if (lane >= d) inc += n;
    }
    int ex = inc - cnt_l;
    int T  = __shfl_sync(0xffffffffu, inc, 31);
    for (int i = 0; i < cnt_l; i++) {
        int s = ex + i;
        if (s < ADDR_CAP) s_addr[wid][s] = base_l + i;
    }
    T = min(T, ADDR_CAP);
    __syncwarp();

    // ---- test candidates (2 per lane per round), compact hits to smem ----
    const unsigned lt_mask = (1u << lane) - 1u;
    const float4* items_b = g_items + (size_t)b * NCELL * CELL_CAP;

    int hcnt = 0;
    for (int i0 = 0; i0 < T; i0 += 64) {
        int ia  = i0 + lane;
        int ib2 = i0 + 32 + lane;
        bool hita = false, hitb = false;
        int ka = 0, kb2 = 0;
        if (ia < T) {
            float4 kv = items_b[s_addr[wid][ia]];
            // strict f32, no FMA, left-to-right — matches jax boundaries
            float dx = __fsub_rn(qx, kv.x);
            float dy = __fsub_rn(qy, kv.y);
            float dz = __fsub_rn(qz, kv.z);
            float d2 = __fadd_rn(__fadd_rn(__fmul_rn(dx, dx),
                                           __fmul_rn(dy, dy)),
                                 __fmul_rn(dz, dz));
            hita = d2 < r2;
            ka   = __float_as_int(kv.w);
        }
        if (ib2 < T) {
            float4 kv = items_b[s_addr[wid][ib2]];
            float dx = __fsub_rn(qx, kv.x);
            float dy = __fsub_rn(qy, kv.y);
            float dz = __fsub_rn(qz, kv.z);
            float d2 = __fadd_rn(__fadd_rn(__fmul_rn(dx, dx),
                                           __fmul_rn(dy, dy)),
                                 __fmul_rn(dz, dz));
            hitb = d2 < r2;
            kb2  = __float_as_int(kv.w);
        }
        unsigned m0 = __ballot_sync(0xffffffffu, hita);
        unsigned m1 = __ballot_sync(0xffffffffu, hitb);
        if (hita) {
            int slot = hcnt + __popc(m0 & lt_mask);
            if (slot < HIT_CAP) s_hbuf[wid][slot] = ka;
        }
        int base1 = hcnt + __popc(m0);
        if (hitb) {
            int slot = base1 + __popc(m1 & lt_mask);
            if (slot < HIT_CAP) s_hbuf[wid][slot] = kb2;
        }
        hcnt = base1 + __popc(m1);
    }
    hcnt = min(hcnt, HIT_CAP);
    __syncwarp();

    float* op = out + ((size_t)b * BQ_N1 + q) * BQ_K;

    if (hcnt <= 64) {
        // ---- common path: 64-wide bitonic sort (2 regs/lane) ----
        int v[2];
        #pragma unroll
        for (int r = 0; r < 2; r++) {
            int e = lane + 32 * r;
            v[r] = (e < hcnt) ? s_hbuf[wid][e] : 0x7FFFFFFF;
        }
        #pragma unroll
        for (int k = 2; k <= 64; k <<= 1) {
            #pragma unroll
            for (int j = 64; j > 0; j >>= 1) {
                if (j >= k) continue;
                if (j < 32) {
                    #pragma unroll
                    for (int r = 0; r < 2; r++) {
                        int other = __shfl_xor_sync(0xffffffffu, v[r], j);
                        bool up    = (((lane + 32 * r) & k) == 0);
                        bool lower = ((lane & j) == 0);
                        int lo = min(v[r], other), hi = max(v[r], other);
                        v[r] = (lower == up) ? lo : hi;
                    }
                } else {            // j == 32: pair (lane, lane+32) in-lane
                    bool up = ((lane & k) == 0);     // k==64 -> always true
                    int lo = min(v[0], v[1]), hi = max(v[0], v[1]);
                    v[0] = up ? lo : hi;
                    v[1] = up ? hi : lo;
                }
            }
        }
        int minv = __shfl_sync(0xffffffffu, v[0], 0);
        int fill = (hcnt > 0) ? minv : 0;
        int e0 = lane, e1 = lane + 32;
        op[e0] = (float)((e0 < hcnt) ? v[0] : fill);
        op[e1] = (float)((e1 < hcnt) ? v[1] : fill);
    } else {
        // ---- rare path: full 128-wide bitonic sort (4 regs/lane) ----
        int v[4];
        #pragma unroll
        for (int r = 0; r < 4; r++) {
            int e = lane + 32 * r;
            v[r] = (e < hcnt) ? s_hbuf[wid][e] : 0x7FFFFFFF;
        }
        #pragma unroll
        for (int k = 2; k <= 128; k <<= 1) {
            #pragma unroll
            for (int j = 64; j > 0; j >>= 1) {
                if (j >= k) continue;
                if (j < 32) {
                    #pragma unroll
                    for (int r = 0; r < 4; r++) {
                        int other = __shfl_xor_sync(0xffffffffu, v[r], j);
                        bool up    = (((lane + 32 * r) & k) == 0);
                        bool lower = ((lane & j) == 0);
                        int lo = min(v[r], other), hi = max(v[r], other);
                        v[r] = (lower == up) ? lo : hi;
                    }
                } else {
                    int rd = j >> 5;
                    #pragma unroll
                    for (int r = 0; r < 4; r++) {
                        if ((r & rd) == 0) {
                            int r2i = r | rd;
                            bool up = (((lane + 32 * r) & k) == 0);
                            int a = v[r], bb = v[r2i];
                            int lo = min(a, bb), hi = max(a, bb);
                            v[r]   = up ? lo : hi;
                            v[r2i] = up ? hi : lo;
                        }
                    }
                }
            }
        }
        int minv = __shfl_sync(0xffffffffu, v[0], 0);
        int fill = (hcnt > 0) ? minv : 0;
        int e0 = lane, e1 = lane + 32;
        op[e0] = (float)((e0 < hcnt) ? v[0] : fill);
        op[e1] = (float)((e1 < hcnt) ? v[1] : fill);
    }
}

extern "C" void kernel_launch(void* const* d_in, const int* in_sizes, int n_in,
                              void* d_out, int out_size)
{
    const float* query = (const float*)d_in[0];
    const float* key   = (const float*)d_in[1];
    if (n_in >= 2 && in_sizes[0] > in_sizes[1]) {   // belt-and-braces
        key   = (const float*)d_in[0];
        query = (const float*)d_in[1];
    }
    float* out = (float*)d_out;

    void* counts_ptr = nullptr;
    cudaGetSymbolAddress(&counts_ptr, g_counts);
    cudaMemsetAsync(counts_ptr, 0, sizeof(int) * BQ_B * NCELL, 0);

    bq_scatter_kernel<<<BQ_B * BQ_N2 / 256, 256>>>(key);
    bq_query_kernel<<<BQ_B * BQ_N1 / 8, 256>>>(query, out);
}

// round 16
// speedup vs baseline: 1.4168x; 1.0173x over previous
#include <cuda_runtime.h>
#include <cstdint>

// BallQuery via uniform grid, 3 graph nodes with PDL overlap:
//   1) cudaMemsetAsync zero of cell counters (memset node)
//   2) scatter kernel (128 blocks, barrier-free)
//   3) query kernel (PDL secondary): prologue overlaps scatter; syncs on the
//      grid only before reading g_counts. Lane-parallel pruned cell list,
//      2-per-lane ballot compaction, dual-width 64/128 bitonic sort.
// B=4, N1=2048, N2=8192, K=64, radius 0.1, output float32 (index as float).

#define BQ_B      4
#define BQ_N1     2048
#define BQ_N2     8192
#define BQ_K      64
#define GRID      10
#define NCELL     (GRID * GRID * GRID)
#define CELL_CAP  64
#define ADDR_CAP  512
#define HIT_CAP   128

__device__ static int    g_counts[BQ_B * NCELL];
__device__ static float4 g_items[BQ_B * NCELL * CELL_CAP];

__global__ __launch_bounds__(256)
void bq_scatter_kernel(const float* __restrict__ key)
{
    const int tid = blockIdx.x * 256 + threadIdx.x;   // exactly 32768 threads
    int b = tid >> 13;
    int j = tid & (BQ_N2 - 1);
    const float* kp = key + (size_t)tid * 3;
    float x = kp[0], y = kp[1], z = kp[2];
    int cx = min((int)(x * 10.0f), GRID - 1);
    int cy = min((int)(y * 10.0f), GRID - 1);
    int cz = min((int)(z * 10.0f), GRID - 1);
    int cell = (cz * GRID + cy) * GRID + cx;
    int slot = atomicAdd(&g_counts[b * NCELL + cell], 1);
    if (slot < CELL_CAP)
        g_items[(b * NCELL + cell) * CELL_CAP + slot] =
            make_float4(x, y, z, __int_as_float(j));
}

__global__ __launch_bounds__(256)
void bq_query_kernel(const float* __restrict__ query,
                     float* __restrict__ out)
{
    __shared__ int s_addr[8][ADDR_CAP];
    __shared__ int s_hbuf[8][HIT_CAP];

    const int wid  = threadIdx.x >> 5;
    const int lane = threadIdx.x & 31;
    const int w    = blockIdx.x * 8 + wid;       // query id
    const int b    = w / BQ_N1;
    const int q    = w - b * BQ_N1;

    // ---- prologue: independent of the grid build (overlaps scatter) ----
    const float* qp = query + (size_t)w * 3;
    const float qx = qp[0];
    const float qy = qp[1];
    const float qz = qp[2];

    const int cx = min((int)(qx * 10.0f), GRID - 1);
    const int cy = min((int)(qy * 10.0f), GRID - 1);
    const int cz = min((int)(qz * 10.0f), GRID - 1);

    const float r2 = 0.1f * 0.1f;                // jnp.float32(0.1)**2

    // Per-lane neighbor cell + conservative box-distance prune (query-only).
    int cell_l = -1;
    if (lane < 27) {
        int x = cx + (lane % 3) - 1;
        int y = cy + ((lane / 3) % 3) - 1;
        int z = cz + (lane / 9) - 1;
        if (x >= 0 && x < GRID && y >= 0 && y < GRID && z >= 0 && z < GRID) {
            // pad 1e-5 >> ~1e-6 fuzz of int(x*10.f) cell assignment
            float lox = x * 0.1f - 1e-5f, hix = x * 0.1f + 0.1f + 1e-5f;
            float loy = y * 0.1f - 1e-5f, hiy = y * 0.1f + 0.1f + 1e-5f;
            float loz = z * 0.1f - 1e-5f, hiz = z * 0.1f + 0.1f + 1e-5f;
            float ddx = fmaxf(fmaxf(lox - qx, qx - hix), 0.0f);
            float ddy = fmaxf(fmaxf(loy - qy, qy - hiy), 0.0f);
            float ddz = fmaxf(fmaxf(loz - qz, qz - hiz), 0.0f);
            float md2 = ddx * ddx + ddy * ddy + ddz * ddz;
            if (md2 < r2) cell_l = (z * GRID + y) * GRID + x;
        }
    }

    // ---- PDL: wait for the scatter grid before touching g_counts/g_items ----
    cudaGridDependencySynchronize();

    int cnt_l = 0, base_l = 0;
    if (cell_l >= 0) {
        cnt_l  = min(g_counts[b * NCELL + cell_l], CELL_CAP);
        base_l = cell_l * CELL_CAP;
    }
    int inc = cnt_l;
    #pragma unroll
    for (int d = 1; d < 32; d <<= 1) {
        int n = __shfl_up_sync(0xffffffffu, inc, d);
        if (lane >= d) inc += n;
    }
    int ex = inc - cnt_l;
    int T  = __shfl_sync(0xffffffffu, inc, 31);
    for (int i = 0; i < cnt_l; i++) {
        int s = ex + i;
        if (s < ADDR_CAP) s_addr[wid][s] = base_l + i;
    }
    T = min(T, ADDR_CAP);
    __syncwarp();

    // ---- test candidates (2 per lane per round), compact hits to smem ----
    const unsigned lt_mask = (1u << lane) - 1u;
    const float4* items_b = g_items + (size_t)b * NCELL * CELL_CAP;

    int hcnt = 0;
    for (int i0 = 0; i0 < T; i0 += 64) {
        int ia  = i0 + lane;
        int ib2 = i0 + 32 + lane;
        bool hita = false, hitb = false;
        int ka = 0, kb2 = 0;
        if (ia < T) {
            float4 kv = items_b[s_addr[wid][ia]];
            // strict f32, no FMA, left-to-right — matches jax boundaries
            float dx = __fsub_rn(qx, kv.x);
            float dy = __fsub_rn(qy, kv.y);
            float dz = __fsub_rn(qz, kv.z);
            float d2 = __fadd_rn(__fadd_rn(__fmul_rn(dx, dx),
                                           __fmul_rn(dy, dy)),
                                 __fmul_rn(dz, dz));
            hita = d2 < r2;
            ka   = __float_as_int(kv.w);
        }
        if (ib2 < T) {
            float4 kv = items_b[s_addr[wid][ib2]];
            float dx = __fsub_rn(qx, kv.x);
            float dy = __fsub_rn(qy, kv.y);
            float dz = __fsub_rn(qz, kv.z);
            float d2 = __fadd_rn(__fadd_rn(__fmul_rn(dx, dx),
                                           __fmul_rn(dy, dy)),
                                 __fmul_rn(dz, dz));
            hitb = d2 < r2;
            kb2  = __float_as_int(kv.w);
        }
        unsigned m0 = __ballot_sync(0xffffffffu, hita);
        unsigned m1 = __ballot_sync(0xffffffffu, hitb);
        if (hita) {
            int slot = hcnt + __popc(m0 & lt_mask);
            if (slot < HIT_CAP) s_hbuf[wid][slot] = ka;
        }
        int base1 = hcnt + __popc(m0);
        if (hitb) {
            int slot = base1 + __popc(m1 & lt_mask);
            if (slot < HIT_CAP) s_hbuf[wid][slot] = kb2;
        }
        hcnt = base1 + __popc(m1);
    }
    hcnt = min(hcnt, HIT_CAP);
    __syncwarp();

    float* op = out + ((size_t)b * BQ_N1 + q) * BQ_K;

    if (hcnt <= 64) {
        // ---- common path: 64-wide bitonic sort (2 regs/lane) ----
        int v[2];
        #pragma unroll
        for (int r = 0; r < 2; r++) {
            int e = lane + 32 * r;
            v[r] = (e < hcnt) ? s_hbuf[wid][e] : 0x7FFFFFFF;
        }
        #pragma unroll
        for (int k = 2; k <= 64; k <<= 1) {
            #pragma unroll
            for (int j = 64; j > 0; j >>= 1) {
                if (j >= k) continue;
                if (j < 32) {
                    #pragma unroll
                    for (int r = 0; r < 2; r++) {
                        int other = __shfl_xor_sync(0xffffffffu, v[r], j);
                        bool up    = (((lane + 32 * r) & k) == 0);
                        bool lower = ((lane & j) == 0);
                        int lo = min(v[r], other), hi = max(v[r], other);
                        v[r] = (lower == up) ? lo : hi;
                    }
                } else {            // j == 32: pair (lane, lane+32) in-lane
                    bool up = ((lane & k) == 0);     // k==64 -> always true
                    int lo = min(v[0], v[1]), hi = max(v[0], v[1]);
                    v[0] = up ? lo : hi;
                    v[1] = up ? hi : lo;
                }
            }
        }
        int minv = __shfl_sync(0xffffffffu, v[0], 0);
        int fill = (hcnt > 0) ? minv : 0;
        int e0 = lane, e1 = lane + 32;
        op[e0] = (float)((e0 < hcnt) ? v[0] : fill);
        op[e1] = (float)((e1 < hcnt) ? v[1] : fill);
    } else {
        // ---- rare path: full 128-wide bitonic sort (4 regs/lane) ----
        int v[4];
        #pragma unroll
        for (int r = 0; r < 4; r++) {
            int e = lane + 32 * r;
            v[r] = (e < hcnt) ? s_hbuf[wid][e] : 0x7FFFFFFF;
        }
        #pragma unroll
        for (int k = 2; k <= 128; k <<= 1) {
            #pragma unroll
            for (int j = 64; j > 0; j >>= 1) {
                if (j >= k) continue;
                if (j < 32) {
                    #pragma unroll
                    for (int r = 0; r < 4; r++) {
                        int other = __shfl_xor_sync(0xffffffffu, v[r], j);
                        bool up    = (((lane + 32 * r) & k) == 0);
                        bool lower = ((lane & j) == 0);
                        int lo = min(v[r], other), hi = max(v[r], other);
                        v[r] = (lower == up) ? lo : hi;
                    }
                } else {
                    int rd = j >> 5;
                    #pragma unroll
                    for (int r = 0; r < 4; r++) {
                        if ((r & rd) == 0) {
                            int r2i = r | rd;
                            bool up = (((lane + 32 * r) & k) == 0);
                            int a = v[r], bb = v[r2i];
                            int lo = min(a, bb), hi = max(a, bb);
                            v[r]   = up ? lo : hi;
                            v[r2i] = up ? hi : lo;
                        }
                    }
                }
            }
        }
        int minv = __shfl_sync(0xffffffffu, v[0], 0);
        int fill = (hcnt > 0) ? minv : 0;
        int e0 = lane, e1 = lane + 32;
        op[e0] = (float)((e0 < hcnt) ? v[0] : fill);
        op[e1] = (float)((e1 < hcnt) ? v[1] : fill);
    }
}

extern "C" void kernel_launch(void* const* d_in, const int* in_sizes, int n_in,
                              void* d_out, int out_size)
{
    const float* query = (const float*)d_in[0];
    const float* key   = (const float*)d_in[1];
    if (n_in >= 2 && in_sizes[0] > in_sizes[1]) {   // belt-and-braces
        key   = (const float*)d_in[0];
        query = (const float*)d_in[1];
    }
    float* out = (float*)d_out;

    void* counts_ptr = nullptr;
    cudaGetSymbolAddress(&counts_ptr, g_counts);
    cudaMemsetAsync(counts_ptr, 0, sizeof(int) * BQ_B * NCELL, 0);

    bq_scatter_kernel<<<BQ_B * BQ_N2 / 256, 256>>>(key);

    // Query kernel as PDL secondary: launches while scatter drains; its
    // prologue overlaps; cudaGridDependencySynchronize() gates grid reads.
    cudaLaunchConfig_t cfg = {};
    cfg.gridDim  = dim3(BQ_B * BQ_N1 / 8);
    cfg.blockDim = dim3(256);
    cfg.dynamicSmemBytes = 0;
    cfg.stream = 0;
    cudaLaunchAttribute attrs[1];
    attrs[0].id = cudaLaunchAttributeProgrammaticStreamSerialization;
    attrs[0].val.programmaticStreamSerializationAllowed = 1;
    cfg.attrs = attrs;
    cfg.numAttrs = 1;
    cudaLaunchKernelEx(&cfg, bq_query_kernel, query, out);
}